// round 16
// baseline (speedup 1.0000x reference)
#include <cuda_runtime.h>
#include <cuda_bf16.h>
#include <cuda_fp16.h>
#include <cstdint>

// Problem constants (fixed shapes from the reference)
#define BB   8
#define NN   12288
#define NTOK 3072
#define CC   256
#define COUT 512
#define HH   128
#define WW   96
#define HWC  (HH*WW)        // 12288 cells
#define H2   64
#define W2   48
#define HW2  (H2*W2)        // 3072 cells
#define MROWS (BB*NTOK)     // 24576
#define NTOT  (BB*NN)       // 98304
#define CAP  32             // max tokens per map cell (lambda=1 Poisson)

// ---------------- scratch (device globals; no allocation allowed) ----------
__device__ __half g_map [(size_t)BB*HWC*CC]; // NORMALIZED map in fp16 (50 MB)
__device__ float g_conv[(size_t)BB*HW2*CC];   // depthwise conv output (b, cell2, c)
__device__ float g_num [(size_t)BB*NTOK*CC];  // fused numerator accumulator
__device__ float g_den [BB*NTOK];
__device__ float g_stats1[2*CC];              // sum, sumsq per C channel
__device__ float g_stats2[2*COUT];            // sum, sumsq per CO channel
__device__ float g_bias[COUT];                // BN1-folded bias

// per-cell token buckets (direct-slot, capacity CAP)
__device__ int g_bcnt[BB*HWC];                // tokens per cell (zeroed each call)
__device__ int g_brec[(size_t)BB*HWC*CAP];    // x source row (global) per slot

// packed bf16 operands: A2 = [Ahi | Alo] per row (M x 512), B2 = [Bhi | Blo] (512 x 512)
__device__ __align__(16) __nv_bfloat16 g_A2[(size_t)MROWS*512];
__device__ __align__(16) __nv_bfloat16 g_B2[(size_t)COUT*512];

// ---------------- helpers ----------------
__device__ __forceinline__ uint32_t smem_to_u32(const void* p) {
    uint32_t a;
    asm("{ .reg .u64 t; cvta.to.shared.u64 t, %1; cvt.u32.u64 %0, t; }" : "=r"(a) : "l"(p));
    return a;
}
__device__ __forceinline__ int grid_cell(float lx, float ly, int h, int w) {
    lx = fminf(fmaxf(lx, -1.0f), 1.0f);
    ly = fminf(fmaxf(ly, -1.0f), 1.0f);
    float fx = __fadd_rn(__fmul_rn(__fmul_rn(0.5f, __fadd_rn(lx, 1.0f)), (float)w), -0.5f);
    float fy = __fadd_rn(__fmul_rn(__fmul_rn(0.5f, __fadd_rn(ly, 1.0f)), (float)h), -0.5f);
    int xi = __float2int_rn(fx);   // round-to-nearest-even matches jnp.round
    int yi = __float2int_rn(fy);
    xi = min(max(xi, 0), w - 1);
    yi = min(max(yi, 0), h - 1);
    return xi + yi * w;
}
// SW128 swizzle (Swizzle<3,4,3>) on within-tile byte offsets (128B rows)
__device__ __forceinline__ int swz(int byte) { return byte ^ ((byte >> 3) & 0x70); }

__device__ __forceinline__ void cp16(uint32_t s, const void* g) {
    asm volatile("cp.async.cg.shared.global [%0], [%1], 16;" :: "r"(s), "l"(g));
}
__device__ __forceinline__ void ldmx4(uint32_t* r, uint32_t addr) {
    asm volatile("ldmatrix.sync.aligned.m8n8.x4.shared.b16 {%0,%1,%2,%3}, [%4];"
        : "=r"(r[0]), "=r"(r[1]), "=r"(r[2]), "=r"(r[3]) : "r"(addr));
}
__device__ __forceinline__ void mma16816(float* c, const uint32_t* a, const uint32_t* b) {
    asm volatile("mma.sync.aligned.m16n8k16.row.col.f32.bf16.bf16.f32 "
        "{%0,%1,%2,%3}, {%4,%5,%6,%7}, {%8,%9}, {%0,%1,%2,%3};"
        : "+f"(c[0]), "+f"(c[1]), "+f"(c[2]), "+f"(c[3])
        : "r"(a[0]), "r"(a[1]), "r"(a[2]), "r"(a[3]), "r"(b[0]), "r"(b[1]));
}
// vectorized global reduction (sm_90+): 4 floats, one REDG
__device__ __forceinline__ void red4(float* addr, float4 v) {
    asm volatile("red.global.add.v4.f32 [%0], {%1,%2,%3,%4};"
        :: "l"(addr), "f"(v.x), "f"(v.y), "f"(v.z), "f"(v.w) : "memory");
}
__device__ __forceinline__ uint32_t pack2bf(float a, float b) {
    __nv_bfloat16 x = __float2bfloat16(a), y = __float2bfloat16(b);
    return (uint32_t)__bfloat16_as_ushort(x) | ((uint32_t)__bfloat16_as_ushort(y) << 16);
}

// ---------------- kernels ----------------
__global__ void k_zero() {
    size_t i = (size_t)blockIdx.x * blockDim.x + threadIdx.x;
    size_t stride = (size_t)gridDim.x * blockDim.x;
    const float4 z = make_float4(0.f, 0.f, 0.f, 0.f);
    float4* n4 = (float4*)g_num;
    for (size_t k = i; k < (size_t)BB*NTOK*CC/4; k += stride) n4[k] = z;
    float4* d4 = (float4*)g_den;
    for (size_t k = i; k < (size_t)(BB*NTOK/4); k += stride) d4[k] = z;
    int4* b4 = (int4*)g_bcnt;
    const int4 zi = make_int4(0, 0, 0, 0);
    for (size_t k = i; k < (size_t)(BB*HWC/4); k += stride) b4[k] = zi;
    if (i < 2*CC)  g_stats1[i] = 0.f;
    if (i < 2*COUT) g_stats2[i] = 0.f;
}

// Bucket fill: slot-assign each token to its map cell; also den = sum_w per tgt.
__global__ void k_fill(const float* __restrict__ loc,
                       const int*   __restrict__ idx_agg,
                       const int*   __restrict__ idx_agg_t,
                       const float* __restrict__ wgt_t) {
    int tok = blockIdx.x * 256 + threadIdx.x;
    int b = tok / NN;
    float lx = loc[2*tok + 0], ly = loc[2*tok + 1];
    int gcell = b*HWC + grid_cell(lx, ly, HH, WW);
    int slot = atomicAdd(&g_bcnt[gcell], 1);
    if (slot < CAP) g_brec[(size_t)gcell*CAP + slot] = b*NN + idx_agg[tok];
    atomicAdd(&g_den[b*NTOK + idx_agg_t[tok]], wgt_t[tok]);
}

// token2map as a GATHER: per cell, sum bucket's x rows, normalize, store fp16.
// Block = 4 cells x 64 threads (4 channels each).
__global__ void __launch_bounds__(256) k_mapgather(const float* __restrict__ x) {
    int cell = blockIdx.x * 4 + (threadIdx.x >> 6);   // global cell b*HWC+...
    int q = (threadIdx.x & 63) * 4;
    int cnt = g_bcnt[cell];
    int n = min(cnt, CAP);
    const int* rec = &g_brec[(size_t)cell*CAP];
    float4 acc = make_float4(0.f, 0.f, 0.f, 0.f);
    for (int j = 0; j < n; j++) {
        int src = rec[j];
        float4 xv = *(const float4*)&x[(size_t)src*CC + q];
        acc.x += xv.x; acc.y += xv.y; acc.z += xv.z; acc.w += xv.w;
    }
    float inv = 1.0f / ((float)cnt + 1e-6f);
    __half2 p0 = __floats2half2_rn(acc.x * inv, acc.y * inv);
    __half2 p1 = __floats2half2_rn(acc.z * inv, acc.w * inv);
    uint2 pk;
    pk.x = *(uint32_t*)&p0;
    pk.y = *(uint32_t*)&p1;
    *(uint2*)&g_map[(size_t)cell*CC + q] = pk;
}

// depthwise 3x3 stride-2 conv on the fp16 pre-normalized map (fp32 math).
// 2 outputs per thread (5-column shared window) for low register pressure /
// high occupancy. Block = 8 output pixels x 64 channel quads. Reversed order.
__global__ void __launch_bounds__(256) k_dwconv(const float* __restrict__ wc) {
    __shared__ float wsm[9*CC];
    int t = threadIdx.x;
    #pragma unroll
    for (int i = 0; i < 9; i++) {
        int idx = t + i*256;   // 2304 total
        int k = idx / CC, c = idx - k*CC;
        wsm[k*CC + c] = wc[c*9 + k];
    }
    int blk = (BB*H2*6 - 1) - blockIdx.x;   // reversed order; 6 segs/row
    int b = blk / (H2*6);
    int rem = blk - b*(H2*6);
    int y2 = rem / 6;
    int x0 = (rem - y2*6) * 8;           // output x base (0,8,...,40)
    __syncthreads();

    int g = t >> 6;                      // 0..3: 2 outputs each
    int q = (t & 63) * 4;                // channel quad
    int xb = x0 + g*2;                   // outputs xb, xb+1
    float4 a0 = make_float4(0.f,0.f,0.f,0.f);
    float4 a1 = make_float4(0.f,0.f,0.f,0.f);

    #pragma unroll
    for (int ky = 0; ky < 3; ky++) {
        int y = 2*y2 - 1 + ky;
        if ((unsigned)y >= HH) continue;
        float4 mv[5];                    // input cols 2*xb-1 .. 2*xb+3
        #pragma unroll
        for (int j = 0; j < 5; j++) {
            int xx = 2*xb - 1 + j;
            if ((unsigned)xx < WW) {
                uint2 raw = *(const uint2*)&g_map[((size_t)(b*HWC + y*WW + xx))*CC + q];
                float2 lo = __half22float2(*(__half2*)&raw.x);
                float2 hi = __half22float2(*(__half2*)&raw.y);
                mv[j] = make_float4(lo.x, lo.y, hi.x, hi.y);
            } else {
                mv[j] = make_float4(0.f,0.f,0.f,0.f);
            }
        }
        #pragma unroll
        for (int kx = 0; kx < 3; kx++) {
            float4 w4 = *(const float4*)&wsm[(ky*3 + kx)*CC + q];
            a0.x += mv[kx].x * w4.x;   a0.y += mv[kx].y * w4.y;
            a0.z += mv[kx].z * w4.z;   a0.w += mv[kx].w * w4.w;
            a1.x += mv[kx+2].x * w4.x; a1.y += mv[kx+2].y * w4.y;
            a1.z += mv[kx+2].z * w4.z; a1.w += mv[kx+2].w * w4.w;
        }
    }
    size_t pix0 = (size_t)b*HW2 + y2*W2 + xb;
    *(float4*)&g_conv[pix0*CC + q]       = a0;
    *(float4*)&g_conv[(pix0 + 1)*CC + q] = a1;
}

// Combined scatter of (x*dw_skip + conv)*w into g_num — ONE red4 stream.
__global__ void __launch_bounds__(256) k_scatter2(
        const float* __restrict__ x,
        const float* __restrict__ loc,
        const int*   __restrict__ idx_agg,
        const int*   __restrict__ idx_agg_t,
        const float* __restrict__ wgt_t,
        const float* __restrict__ dw_skip) {
    int tok0 = blockIdx.x * 16 + (threadIdx.x >> 5) * 2;
    int lane = threadIdx.x & 31;
    float4 d0 = *(const float4*)&dw_skip[lane*4];
    float4 d1 = *(const float4*)&dw_skip[128 + lane*4];
    #pragma unroll
    for (int u = 0; u < 2; u++) {
        int tok = tok0 + u;
        int b = tok / NN;
        float lx = loc[2*tok + 0], ly = loc[2*tok + 1];
        int cell2 = grid_cell(lx, ly, H2, W2);
        int src   = idx_agg[tok];
        int tgt   = idx_agg_t[tok];
        float w   = wgt_t[tok];
        const float* xr = &x[((size_t)b*NN + src)*CC];
        const float* fr = &g_conv[((size_t)b*HW2 + cell2)*CC];
        float* nr = &g_num[((size_t)b*NTOK + tgt)*CC];
        float4 xv0 = *(const float4*)&xr[lane*4];
        float4 xv1 = *(const float4*)&xr[128 + lane*4];
        float4 f0  = *(const float4*)&fr[lane*4];
        float4 f1  = *(const float4*)&fr[128 + lane*4];
        float4 v0 = make_float4((xv0.x*d0.x + f0.x)*w, (xv0.y*d0.y + f0.y)*w,
                                (xv0.z*d0.z + f0.z)*w, (xv0.w*d0.w + f0.w)*w);
        float4 v1 = make_float4((xv1.x*d1.x + f1.x)*w, (xv1.y*d1.y + f1.y)*w,
                                (xv1.z*d1.z + f1.z)*w, (xv1.w*d1.w + f1.w)*w);
        red4(&nr[lane*4], v0);
        red4(&nr[128 + lane*4], v1);
    }
}

// Fused BN1 stats + A2 pack: one pass over g_num.
__global__ void __launch_bounds__(256) k_bn1pack() {
    int t = threadIdx.x;
    int rr = t >> 6;          // 0..3
    int g  = t & 63;          // channel quad
    int r0 = blockIdx.x * 64;
    float s[4]  = {0.f,0.f,0.f,0.f};
    float s2[4] = {0.f,0.f,0.f,0.f};
    #pragma unroll 4
    for (int i = 0; i < 16; i++) {
        int r = r0 + i*4 + rr;
        float rden = 1.0f / (g_den[r] + 1e-6f);
        float4 v = *(const float4*)&g_num[(size_t)r*CC + g*4];
        v.x *= rden; v.y *= rden; v.z *= rden; v.w *= rden;
        __nv_bfloat16 h0 = __float2bfloat16(v.x), h1 = __float2bfloat16(v.y);
        __nv_bfloat16 h2 = __float2bfloat16(v.z), h3 = __float2bfloat16(v.w);
        uint2 hi, lo;
        hi.x = (uint32_t)__bfloat16_as_ushort(h0) | ((uint32_t)__bfloat16_as_ushort(h1) << 16);
        hi.y = (uint32_t)__bfloat16_as_ushort(h2) | ((uint32_t)__bfloat16_as_ushort(h3) << 16);
        lo.x = pack2bf(v.x - __bfloat162float(h0), v.y - __bfloat162float(h1));
        lo.y = pack2bf(v.z - __bfloat162float(h2), v.w - __bfloat162float(h3));
        *(uint2*)&g_A2[(size_t)r*512 + g*4]       = hi;
        *(uint2*)&g_A2[(size_t)r*512 + 256 + g*4] = lo;
        s[0] += v.x; s[1] += v.y; s[2] += v.z; s[3] += v.w;
        s2[0] += v.x*v.x; s2[1] += v.y*v.y; s2[2] += v.z*v.z; s2[3] += v.w*v.w;
    }
    __shared__ float sred[4*CC], s2red[4*CC];
    #pragma unroll
    for (int j = 0; j < 4; j++) {
        sred[rr*CC + g*4 + j]  = s[j];
        s2red[rr*CC + g*4 + j] = s2[j];
    }
    __syncthreads();
    if (rr == 0) {
        #pragma unroll
        for (int j = 0; j < 4; j++) {
            int c = g*4 + j;
            float ts  = sred[c] + sred[CC + c] + sred[2*CC + c] + sred[3*CC + c];
            float ts2 = s2red[c] + s2red[CC + c] + s2red[2*CC + c] + s2red[3*CC + c];
            atomicAdd(&g_stats1[c], ts);
            atomicAdd(&g_stats1[CC + c], ts2);
        }
    }
}

// Fused: fold BN1 into 1x1 conv weights AND pack B2 hi/lo; also bias reduction.
__global__ void k_foldpack(const float* __restrict__ conv_w,
                           const float* __restrict__ g1,
                           const float* __restrict__ b1) {
    __shared__ float red[CC];
    int o = blockIdx.x, c = threadIdx.x;
    const float inv = 1.0f / (float)MROWS;
    float mean = g_stats1[c] * inv;
    float var  = g_stats1[CC + c] * inv - mean * mean;
    float a = g1[c] * rsqrtf(var + 1e-5f);
    float d = b1[c] - mean * a;
    float w = conv_w[o*CC + c];
    float wp = w * a;
    __nv_bfloat16 h = __float2bfloat16(wp);
    __nv_bfloat16 l = __float2bfloat16(wp - __bfloat162float(h));
    g_B2[(size_t)o*512 + c]       = h;
    g_B2[(size_t)o*512 + 256 + c] = l;
    red[c] = d * w;
    __syncthreads();
    for (int s = CC/2; s > 0; s >>= 1) {
        if (c < s) red[c] += red[c + s];
        __syncthreads();
    }
    if (c == 0) g_bias[o] = red[0];
}

// ---------------- bf16 mma.sync GEMM with 3-term split (effective K = 768) --
// PROVEN R11 schedule: 12 iterations over (term, j) pairs, 32KB stages.
#define GSTAGE 32768   // bytes per stage: A 16K + B 16K

__global__ void __launch_bounds__(256) k_gemm_mma(float* __restrict__ out) {
    extern __shared__ unsigned char smraw[];
    uint32_t rawb = smem_to_u32(smraw);
    uint32_t smb = (rawb + 1023) & ~1023u;
    const int tid = threadIdx.x;
    const int wid = tid >> 5, lane = tid & 31;
    const int tile_n = blockIdx.x & 3, tile_m = blockIdx.x >> 2;
    const int warp_m = wid & 3, warp_n = wid >> 2;   // 4 x 2 warp grid

    const __nv_bfloat16* gA = g_A2 + (size_t)tile_m * 128 * 512;
    const __nv_bfloat16* gB = g_B2 + (size_t)tile_n * 128 * 512;

    float acc[2][8][4];
    #pragma unroll
    for (int mt = 0; mt < 2; mt++)
        #pragma unroll
        for (int nt = 0; nt < 8; nt++)
            #pragma unroll
            for (int i = 0; i < 4; i++) acc[mt][nt][i] = 0.f;

    auto load_tiles = [&](int it, int s) {
        int term = it >> 2, j = it & 3;
        int a_k0 = ((term == 2) ? 256 : 0) + j*64;
        int b_k0 = ((term == 1) ? 256 : 0) + j*64;
        uint32_t sa = smb + s*GSTAGE;
        uint32_t sb = sa + 16384;
        #pragma unroll
        for (int i = 0; i < 4; i++) {
            int idx = tid + i*256;
            int r = idx >> 3, kc = idx & 7;
            cp16(sa + swz(r*128 + kc*16), (const char*)(gA + (size_t)r*512 + a_k0) + kc*16);
        }
        #pragma unroll
        for (int i = 0; i < 4; i++) {
            int idx = tid + i*256;
            int r = idx >> 3, kc = idx & 7;
            cp16(sb + swz(r*128 + kc*16), (const char*)(gB + (size_t)r*512 + b_k0) + kc*16);
        }
        asm volatile("cp.async.commit_group;" ::: "memory");
    };

    load_tiles(0, 0);

    for (int it = 0; it < 12; ++it) {
        int s = it & 1;
        if (it + 1 < 12) {
            load_tiles(it + 1, s ^ 1);
            asm volatile("cp.async.wait_group 1;" ::: "memory");
        } else {
            asm volatile("cp.async.wait_group 0;" ::: "memory");
        }
        __syncthreads();

        uint32_t smA = smb + s*GSTAGE;
        uint32_t smB = smA + 16384;
        #pragma unroll
        for (int kt = 0; kt < 4; kt++) {
            uint32_t afr[2][4];
            #pragma unroll
            for (int mt = 0; mt < 2; mt++) {
                int m = warp_m*32 + mt*16 + (lane & 15);
                int kb = kt*32 + ((lane >> 4) << 4);
                ldmx4(afr[mt], smA + swz(m*128 + kb));
            }
            uint32_t bfr[4][4];
            #pragma unroll
            for (int np = 0; np < 4; np++) {
                int n = warp_n*64 + np*16 + (lane & 7) + ((lane >> 4) << 3);
                int kb = kt*32 + (((lane >> 3) & 1) << 4);
                ldmx4(bfr[np], smB + swz(n*128 + kb));
            }
            #pragma unroll
            for (int mt = 0; mt < 2; mt++)
                #pragma unroll
                for (int nt = 0; nt < 8; nt++)
                    mma16816(acc[mt][nt], afr[mt], &bfr[nt >> 1][(nt & 1)*2]);
        }
        __syncthreads();
    }

    // epilogue: + bias, write fp32, accumulate BN2 per-channel stats
    float sc[8][2], sc2[8][2];
    #pragma unroll
    for (int nt = 0; nt < 8; nt++)
        #pragma unroll
        for (int j = 0; j < 2; j++) { sc[nt][j] = 0.f; sc2[nt][j] = 0.f; }

    #pragma unroll
    for (int mt = 0; mt < 2; mt++) {
        int row = tile_m*128 + warp_m*32 + mt*16 + (lane >> 2);
        #pragma unroll
        for (int nt = 0; nt < 8; nt++) {
            int col = tile_n*128 + warp_n*64 + nt*8 + ((lane & 3) << 1);
            float b0 = g_bias[col], b1 = g_bias[col + 1];
            float2 v0 = make_float2(acc[mt][nt][0] + b0, acc[mt][nt][1] + b1);
            float2 v1 = make_float2(acc[mt][nt][2] + b0, acc[mt][nt][3] + b1);
            *(float2*)&out[(size_t)row*COUT + col]       = v0;
            *(float2*)&out[(size_t)(row + 8)*COUT + col] = v1;
            sc[nt][0]  += v0.x + v1.x;           sc[nt][1]  += v0.y + v1.y;
            sc2[nt][0] += v0.x*v0.x + v1.x*v1.x; sc2[nt][1] += v0.y*v0.y + v1.y*v1.y;
        }
    }
    #pragma unroll
    for (int off = 4; off < 32; off <<= 1) {
        #pragma unroll
        for (int nt = 0; nt < 8; nt++)
            #pragma unroll
            for (int j = 0; j < 2; j++) {
                sc[nt][j]  += __shfl_xor_sync(0xffffffffu, sc[nt][j],  off);
                sc2[nt][j] += __shfl_xor_sync(0xffffffffu, sc2[nt][j], off);
            }
    }
    if (lane < 4) {
        #pragma unroll
        for (int nt = 0; nt < 8; nt++)
            #pragma unroll
            for (int j = 0; j < 2; j++) {
                int col = tile_n*128 + warp_n*64 + nt*8 + lane*2 + j;
                atomicAdd(&g_stats2[col], sc[nt][j]);
                atomicAdd(&g_stats2[COUT + col], sc2[nt][j]);
            }
    }
}

// BN2 fold + apply + relu fused (per-block recompute of scale/shift)
__global__ void __launch_bounds__(256) k_bn2_apply(float* __restrict__ out,
                                                   const float* __restrict__ g2,
                                                   const float* __restrict__ b2) {
    __shared__ float sa[COUT], sd[COUT];
    int t = threadIdx.x;
    const float inv = 1.0f / (float)MROWS;
    #pragma unroll
    for (int i = t; i < COUT; i += 256) {
        float mean = g_stats2[i] * inv;
        float var  = g_stats2[COUT + i] * inv - mean * mean;
        float a = g2[i] * rsqrtf(var + 1e-5f);
        sa[i] = a;
        sd[i] = b2[i] - mean * a;
    }
    __syncthreads();
    #pragma unroll
    for (int it = 0; it < 6; it++) {
        size_t idx4 = (size_t)blockIdx.x * 256 + t + (size_t)it * 524288;
        int o = (int)(idx4 & (COUT/4 - 1)) * 4;
        float4 v = ((float4*)out)[idx4];
        v.x = fmaxf(0.f, v.x * sa[o+0] + sd[o+0]);
        v.y = fmaxf(0.f, v.y * sa[o+1] + sd[o+1]);
        v.z = fmaxf(0.f, v.z * sa[o+2] + sd[o+2]);
        v.w = fmaxf(0.f, v.w * sa[o+3] + sd[o+3]);
        ((float4*)out)[idx4] = v;
    }
}

// ---------------- launch ----------------
extern "C" void kernel_launch(void* const* d_in, const int* in_sizes, int n_in,
                              void* d_out, int out_size) {
    const float* x     = (const float*)d_in[0];   // (B,N,C)
    const float* loc   = (const float*)d_in[1];   // (B,N,2)
    const int*   idxa  = (const int*)  d_in[2];   // (B,N)
    const int*   idxat = (const int*)  d_in[5];   // (B,N)
    const float* wt    = (const float*)d_in[6];   // (B,N,1)
    const float* dwc   = (const float*)d_in[9];   // (C,1,3,3)
    const float* dws   = (const float*)d_in[10];  // (C,1,1,1)
    const float* g1    = (const float*)d_in[11];
    const float* b1    = (const float*)d_in[12];
    const float* cw    = (const float*)d_in[13];  // (CO,C)
    const float* g2    = (const float*)d_in[14];
    const float* b2    = (const float*)d_in[15];
    float* out = (float*)d_out;

    const int GEMM_SMEM = 2*GSTAGE + 1024;
    cudaFuncSetAttribute(k_gemm_mma, cudaFuncAttributeMaxDynamicSharedMemorySize, GEMM_SMEM);

    k_zero<<<2048, 256>>>();
    k_fill<<<NTOT/256, 256>>>(loc, idxa, idxat, wt);
    k_mapgather<<<BB*HWC/4, 256>>>(x);
    k_dwconv<<<BB*H2*6, 256>>>(dwc);
    k_scatter2<<<NTOT/16, 256>>>(x, loc, idxa, idxat, wt, dws);
    k_bn1pack<<<MROWS/64, 256>>>();
    k_foldpack<<<COUT, CC>>>(cw, g1, b1);
    k_gemm_mma<<<(MROWS/128)*(COUT/128), 256, GEMM_SMEM>>>(out);
    k_bn2_apply<<<2048, 256>>>(out, g2, b2);
}

// round 17
// speedup vs baseline: 1.0175x; 1.0175x over previous
#include <cuda_runtime.h>
#include <cuda_bf16.h>
#include <cuda_fp16.h>
#include <cstdint>

// Problem constants (fixed shapes from the reference)
#define BB   8
#define NN   12288
#define NTOK 3072
#define CC   256
#define COUT 512
#define HH   128
#define WW   96
#define HWC  (HH*WW)        // 12288 cells
#define H2   64
#define W2   48
#define HW2  (H2*W2)        // 3072 cells
#define MROWS (BB*NTOK)     // 24576
#define NTOT  (BB*NN)       // 98304
#define CAP  32             // max tokens per map cell (lambda=1 Poisson)

// ---------------- scratch (device globals; no allocation allowed) ----------
__device__ __half g_map [(size_t)BB*HWC*CC]; // NORMALIZED map in fp16 (50 MB)
__device__ float g_conv[(size_t)BB*HW2*CC];   // depthwise conv output (b, cell2, c)
__device__ float g_num [(size_t)BB*NTOK*CC];  // fused numerator accumulator
__device__ float g_den [BB*NTOK];
__device__ float g_stats1[2*CC];              // sum, sumsq per C channel
__device__ float g_stats2[2*COUT];            // sum, sumsq per CO channel
__device__ float g_bias[COUT];                // BN1-folded bias

// per-cell token buckets (direct-slot, capacity CAP)
__device__ int g_bcnt[BB*HWC];                // tokens per cell (zeroed each call)
__device__ int g_brec[(size_t)BB*HWC*CAP];    // x source row (global) per slot

// packed bf16 operands: A2 = [Ahi | Alo] per row (M x 512), B2 = [Bhi | Blo] (512 x 512)
__device__ __align__(16) __nv_bfloat16 g_A2[(size_t)MROWS*512];
__device__ __align__(16) __nv_bfloat16 g_B2[(size_t)COUT*512];

// ---------------- helpers ----------------
__device__ __forceinline__ uint32_t smem_to_u32(const void* p) {
    uint32_t a;
    asm("{ .reg .u64 t; cvta.to.shared.u64 t, %1; cvt.u32.u64 %0, t; }" : "=r"(a) : "l"(p));
    return a;
}
__device__ __forceinline__ int grid_cell(float lx, float ly, int h, int w) {
    lx = fminf(fmaxf(lx, -1.0f), 1.0f);
    ly = fminf(fmaxf(ly, -1.0f), 1.0f);
    float fx = __fadd_rn(__fmul_rn(__fmul_rn(0.5f, __fadd_rn(lx, 1.0f)), (float)w), -0.5f);
    float fy = __fadd_rn(__fmul_rn(__fmul_rn(0.5f, __fadd_rn(ly, 1.0f)), (float)h), -0.5f);
    int xi = __float2int_rn(fx);   // round-to-nearest-even matches jnp.round
    int yi = __float2int_rn(fy);
    xi = min(max(xi, 0), w - 1);
    yi = min(max(yi, 0), h - 1);
    return xi + yi * w;
}
// SW128 swizzle (Swizzle<3,4,3>) on within-tile byte offsets (128B rows)
__device__ __forceinline__ int swz(int byte) { return byte ^ ((byte >> 3) & 0x70); }

__device__ __forceinline__ void cp16(uint32_t s, const void* g) {
    asm volatile("cp.async.cg.shared.global [%0], [%1], 16;" :: "r"(s), "l"(g));
}
__device__ __forceinline__ void ldmx4(uint32_t* r, uint32_t addr) {
    asm volatile("ldmatrix.sync.aligned.m8n8.x4.shared.b16 {%0,%1,%2,%3}, [%4];"
        : "=r"(r[0]), "=r"(r[1]), "=r"(r[2]), "=r"(r[3]) : "r"(addr));
}
__device__ __forceinline__ void mma16816(float* c, const uint32_t* a, const uint32_t* b) {
    asm volatile("mma.sync.aligned.m16n8k16.row.col.f32.bf16.bf16.f32 "
        "{%0,%1,%2,%3}, {%4,%5,%6,%7}, {%8,%9}, {%0,%1,%2,%3};"
        : "+f"(c[0]), "+f"(c[1]), "+f"(c[2]), "+f"(c[3])
        : "r"(a[0]), "r"(a[1]), "r"(a[2]), "r"(a[3]), "r"(b[0]), "r"(b[1]));
}
// vectorized global reduction (sm_90+): 4 floats, one REDG
__device__ __forceinline__ void red4(float* addr, float4 v) {
    asm volatile("red.global.add.v4.f32 [%0], {%1,%2,%3,%4};"
        :: "l"(addr), "f"(v.x), "f"(v.y), "f"(v.z), "f"(v.w) : "memory");
}
__device__ __forceinline__ uint32_t pack2bf(float a, float b) {
    __nv_bfloat16 x = __float2bfloat16(a), y = __float2bfloat16(b);
    return (uint32_t)__bfloat16_as_ushort(x) | ((uint32_t)__bfloat16_as_ushort(y) << 16);
}

// ---------------- kernels ----------------
__global__ void k_zero() {
    size_t i = (size_t)blockIdx.x * blockDim.x + threadIdx.x;
    size_t stride = (size_t)gridDim.x * blockDim.x;
    const float4 z = make_float4(0.f, 0.f, 0.f, 0.f);
    float4* n4 = (float4*)g_num;
    for (size_t k = i; k < (size_t)BB*NTOK*CC/4; k += stride) n4[k] = z;
    float4* d4 = (float4*)g_den;
    for (size_t k = i; k < (size_t)(BB*NTOK/4); k += stride) d4[k] = z;
    int4* b4 = (int4*)g_bcnt;
    const int4 zi = make_int4(0, 0, 0, 0);
    for (size_t k = i; k < (size_t)(BB*HWC/4); k += stride) b4[k] = zi;
    if (i < 2*CC)  g_stats1[i] = 0.f;
    if (i < 2*COUT) g_stats2[i] = 0.f;
}

// Bucket fill: slot-assign each token to its map cell; also den = sum_w per tgt.
__global__ void k_fill(const float* __restrict__ loc,
                       const int*   __restrict__ idx_agg,
                       const int*   __restrict__ idx_agg_t,
                       const float* __restrict__ wgt_t) {
    int tok = blockIdx.x * 256 + threadIdx.x;
    int b = tok / NN;
    float lx = loc[2*tok + 0], ly = loc[2*tok + 1];
    int gcell = b*HWC + grid_cell(lx, ly, HH, WW);
    int slot = atomicAdd(&g_bcnt[gcell], 1);
    if (slot < CAP) g_brec[(size_t)gcell*CAP + slot] = b*NN + idx_agg[tok];
    atomicAdd(&g_den[b*NTOK + idx_agg_t[tok]], wgt_t[tok]);
}

// token2map as a GATHER: per cell, sum bucket's x rows, normalize, store fp16.
// Block = 4 cells x 64 threads (4 channels each).
__global__ void __launch_bounds__(256) k_mapgather(const float* __restrict__ x) {
    int cell = blockIdx.x * 4 + (threadIdx.x >> 6);   // global cell b*HWC+...
    int q = (threadIdx.x & 63) * 4;
    int cnt = g_bcnt[cell];
    int n = min(cnt, CAP);
    const int* rec = &g_brec[(size_t)cell*CAP];
    float4 acc = make_float4(0.f, 0.f, 0.f, 0.f);
    for (int j = 0; j < n; j++) {
        int src = rec[j];
        float4 xv = *(const float4*)&x[(size_t)src*CC + q];
        acc.x += xv.x; acc.y += xv.y; acc.z += xv.z; acc.w += xv.w;
    }
    float inv = 1.0f / ((float)cnt + 1e-6f);
    __half2 p0 = __floats2half2_rn(acc.x * inv, acc.y * inv);
    __half2 p1 = __floats2half2_rn(acc.z * inv, acc.w * inv);
    uint2 pk;
    pk.x = *(uint32_t*)&p0;
    pk.y = *(uint32_t*)&p1;
    *(uint2*)&g_map[(size_t)cell*CC + q] = pk;
}

// depthwise 3x3 stride-2 conv on the fp16 pre-normalized map (fp32 math).
// 2 outputs per thread (5-column shared window) for low register pressure /
// high occupancy. Block = 8 output pixels x 64 channel quads. Reversed order.
__global__ void __launch_bounds__(256) k_dwconv(const float* __restrict__ wc) {
    __shared__ float wsm[9*CC];
    int t = threadIdx.x;
    #pragma unroll
    for (int i = 0; i < 9; i++) {
        int idx = t + i*256;   // 2304 total
        int k = idx / CC, c = idx - k*CC;
        wsm[k*CC + c] = wc[c*9 + k];
    }
    int blk = (BB*H2*6 - 1) - blockIdx.x;   // reversed order; 6 segs/row
    int b = blk / (H2*6);
    int rem = blk - b*(H2*6);
    int y2 = rem / 6;
    int x0 = (rem - y2*6) * 8;           // output x base (0,8,...,40)
    __syncthreads();

    int g = t >> 6;                      // 0..3: 2 outputs each
    int q = (t & 63) * 4;                // channel quad
    int xb = x0 + g*2;                   // outputs xb, xb+1
    float4 a0 = make_float4(0.f,0.f,0.f,0.f);
    float4 a1 = make_float4(0.f,0.f,0.f,0.f);

    #pragma unroll
    for (int ky = 0; ky < 3; ky++) {
        int y = 2*y2 - 1 + ky;
        if ((unsigned)y >= HH) continue;
        float4 mv[5];                    // input cols 2*xb-1 .. 2*xb+3
        #pragma unroll
        for (int j = 0; j < 5; j++) {
            int xx = 2*xb - 1 + j;
            if ((unsigned)xx < WW) {
                uint2 raw = *(const uint2*)&g_map[((size_t)(b*HWC + y*WW + xx))*CC + q];
                float2 lo = __half22float2(*(__half2*)&raw.x);
                float2 hi = __half22float2(*(__half2*)&raw.y);
                mv[j] = make_float4(lo.x, lo.y, hi.x, hi.y);
            } else {
                mv[j] = make_float4(0.f,0.f,0.f,0.f);
            }
        }
        #pragma unroll
        for (int kx = 0; kx < 3; kx++) {
            float4 w4 = *(const float4*)&wsm[(ky*3 + kx)*CC + q];
            a0.x += mv[kx].x * w4.x;   a0.y += mv[kx].y * w4.y;
            a0.z += mv[kx].z * w4.z;   a0.w += mv[kx].w * w4.w;
            a1.x += mv[kx+2].x * w4.x; a1.y += mv[kx+2].y * w4.y;
            a1.z += mv[kx+2].z * w4.z; a1.w += mv[kx+2].w * w4.w;
        }
    }
    size_t pix0 = (size_t)b*HW2 + y2*W2 + xb;
    *(float4*)&g_conv[pix0*CC + q]       = a0;
    *(float4*)&g_conv[(pix0 + 1)*CC + q] = a1;
}

// Combined scatter of (x*dw_skip + conv)*w into g_num — ONE red4 stream.
__global__ void __launch_bounds__(256) k_scatter2(
        const float* __restrict__ x,
        const float* __restrict__ loc,
        const int*   __restrict__ idx_agg,
        const int*   __restrict__ idx_agg_t,
        const float* __restrict__ wgt_t,
        const float* __restrict__ dw_skip) {
    int tok0 = blockIdx.x * 16 + (threadIdx.x >> 5) * 2;
    int lane = threadIdx.x & 31;
    float4 d0 = *(const float4*)&dw_skip[lane*4];
    float4 d1 = *(const float4*)&dw_skip[128 + lane*4];
    #pragma unroll
    for (int u = 0; u < 2; u++) {
        int tok = tok0 + u;
        int b = tok / NN;
        float lx = loc[2*tok + 0], ly = loc[2*tok + 1];
        int cell2 = grid_cell(lx, ly, H2, W2);
        int src   = idx_agg[tok];
        int tgt   = idx_agg_t[tok];
        float w   = wgt_t[tok];
        const float* xr = &x[((size_t)b*NN + src)*CC];
        const float* fr = &g_conv[((size_t)b*HW2 + cell2)*CC];
        float* nr = &g_num[((size_t)b*NTOK + tgt)*CC];
        float4 xv0 = *(const float4*)&xr[lane*4];
        float4 xv1 = *(const float4*)&xr[128 + lane*4];
        float4 f0  = *(const float4*)&fr[lane*4];
        float4 f1  = *(const float4*)&fr[128 + lane*4];
        float4 v0 = make_float4((xv0.x*d0.x + f0.x)*w, (xv0.y*d0.y + f0.y)*w,
                                (xv0.z*d0.z + f0.z)*w, (xv0.w*d0.w + f0.w)*w);
        float4 v1 = make_float4((xv1.x*d1.x + f1.x)*w, (xv1.y*d1.y + f1.y)*w,
                                (xv1.z*d1.z + f1.z)*w, (xv1.w*d1.w + f1.w)*w);
        red4(&nr[lane*4], v0);
        red4(&nr[128 + lane*4], v1);
    }
}

// Fused BN1 stats + A2 pack: one pass over g_num.
__global__ void __launch_bounds__(256) k_bn1pack() {
    int t = threadIdx.x;
    int rr = t >> 6;          // 0..3
    int g  = t & 63;          // channel quad
    int r0 = blockIdx.x * 64;
    float s[4]  = {0.f,0.f,0.f,0.f};
    float s2[4] = {0.f,0.f,0.f,0.f};
    #pragma unroll 4
    for (int i = 0; i < 16; i++) {
        int r = r0 + i*4 + rr;
        float rden = 1.0f / (g_den[r] + 1e-6f);
        float4 v = *(const float4*)&g_num[(size_t)r*CC + g*4];
        v.x *= rden; v.y *= rden; v.z *= rden; v.w *= rden;
        __nv_bfloat16 h0 = __float2bfloat16(v.x), h1 = __float2bfloat16(v.y);
        __nv_bfloat16 h2 = __float2bfloat16(v.z), h3 = __float2bfloat16(v.w);
        uint2 hi, lo;
        hi.x = (uint32_t)__bfloat16_as_ushort(h0) | ((uint32_t)__bfloat16_as_ushort(h1) << 16);
        hi.y = (uint32_t)__bfloat16_as_ushort(h2) | ((uint32_t)__bfloat16_as_ushort(h3) << 16);
        lo.x = pack2bf(v.x - __bfloat162float(h0), v.y - __bfloat162float(h1));
        lo.y = pack2bf(v.z - __bfloat162float(h2), v.w - __bfloat162float(h3));
        *(uint2*)&g_A2[(size_t)r*512 + g*4]       = hi;
        *(uint2*)&g_A2[(size_t)r*512 + 256 + g*4] = lo;
        s[0] += v.x; s[1] += v.y; s[2] += v.z; s[3] += v.w;
        s2[0] += v.x*v.x; s2[1] += v.y*v.y; s2[2] += v.z*v.z; s2[3] += v.w*v.w;
    }
    __shared__ float sred[4*CC], s2red[4*CC];
    #pragma unroll
    for (int j = 0; j < 4; j++) {
        sred[rr*CC + g*4 + j]  = s[j];
        s2red[rr*CC + g*4 + j] = s2[j];
    }
    __syncthreads();
    if (rr == 0) {
        #pragma unroll
        for (int j = 0; j < 4; j++) {
            int c = g*4 + j;
            float ts  = sred[c] + sred[CC + c] + sred[2*CC + c] + sred[3*CC + c];
            float ts2 = s2red[c] + s2red[CC + c] + s2red[2*CC + c] + s2red[3*CC + c];
            atomicAdd(&g_stats1[c], ts);
            atomicAdd(&g_stats1[CC + c], ts2);
        }
    }
}

// Fused: fold BN1 into 1x1 conv weights AND pack B2 hi/lo; also bias reduction.
__global__ void k_foldpack(const float* __restrict__ conv_w,
                           const float* __restrict__ g1,
                           const float* __restrict__ b1) {
    __shared__ float red[CC];
    int o = blockIdx.x, c = threadIdx.x;
    const float inv = 1.0f / (float)MROWS;
    float mean = g_stats1[c] * inv;
    float var  = g_stats1[CC + c] * inv - mean * mean;
    float a = g1[c] * rsqrtf(var + 1e-5f);
    float d = b1[c] - mean * a;
    float w = conv_w[o*CC + c];
    float wp = w * a;
    __nv_bfloat16 h = __float2bfloat16(wp);
    __nv_bfloat16 l = __float2bfloat16(wp - __bfloat162float(h));
    g_B2[(size_t)o*512 + c]       = h;
    g_B2[(size_t)o*512 + 256 + c] = l;
    red[c] = d * w;
    __syncthreads();
    for (int s = CC/2; s > 0; s >>= 1) {
        if (c < s) red[c] += red[c + s];
        __syncthreads();
    }
    if (c == 0) g_bias[o] = red[0];
}

// ---------------- bf16 mma.sync GEMM, 3-term split, A-chunk reuse ----------
// Iteration order: phase 1 (it 0..7): pairs (Ahi_j*Bhi_j, Ahi_j*Blo_j) — A
// loaded once per pair. Phase 2 (it 8..11): Alo_j*Bhi_j. A loads: 8 (was 12).
// Separate double-buffered A slots (by j&1) and B slots (by it&1); 64KB total
// (same footprint as the proven R11 kernel -> 3 CTA/SM). NON-unrolled loop.
__global__ void __launch_bounds__(256) k_gemm_mma(float* __restrict__ out) {
    extern __shared__ unsigned char smraw[];
    uint32_t rawb = smem_to_u32(smraw);
    uint32_t smb = (rawb + 1023) & ~1023u;
    const int tid = threadIdx.x;
    const int wid = tid >> 5, lane = tid & 31;
    const int tile_n = blockIdx.x & 3, tile_m = blockIdx.x >> 2;
    const int warp_m = wid & 3, warp_n = wid >> 2;   // 4 x 2 warp grid

    const __nv_bfloat16* gA = g_A2 + (size_t)tile_m * 128 * 512;
    const __nv_bfloat16* gB = g_B2 + (size_t)tile_n * 128 * 512;

    float acc[2][8][4];
    #pragma unroll
    for (int mt = 0; mt < 2; mt++)
        #pragma unroll
        for (int nt = 0; nt < 8; nt++)
            #pragma unroll
            for (int i = 0; i < 4; i++) acc[mt][nt][i] = 0.f;

    auto load_tiles = [&](int it) {
        bool ph2 = (it >= 8);
        int j = ph2 ? (it - 8) : (it >> 1);
        bool loadA = ph2 || ((it & 1) == 0);
        int a_k0 = (ph2 ? 256 : 0) + j*64;
        int b_k0 = (!ph2 && (it & 1)) ? (256 + j*64) : (j*64);
        if (loadA) {
            uint32_t sa = smb + (j & 1)*16384;
            #pragma unroll
            for (int i = 0; i < 4; i++) {
                int idx = tid + i*256;
                int r = idx >> 3, kc = idx & 7;
                cp16(sa + swz(r*128 + kc*16), (const char*)(gA + (size_t)r*512 + a_k0) + kc*16);
            }
        }
        uint32_t sb = smb + 32768 + (it & 1)*16384;
        #pragma unroll
        for (int i = 0; i < 4; i++) {
            int idx = tid + i*256;
            int r = idx >> 3, kc = idx & 7;
            cp16(sb + swz(r*128 + kc*16), (const char*)(gB + (size_t)r*512 + b_k0) + kc*16);
        }
        asm volatile("cp.async.commit_group;" ::: "memory");
    };

    load_tiles(0);

    for (int it = 0; it < 12; ++it) {
        if (it + 1 < 12) {
            load_tiles(it + 1);
            asm volatile("cp.async.wait_group 1;" ::: "memory");
        } else {
            asm volatile("cp.async.wait_group 0;" ::: "memory");
        }
        __syncthreads();

        int jc = (it >= 8) ? (it - 8) : (it >> 1);
        uint32_t smA = smb + (jc & 1)*16384;
        uint32_t smB = smb + 32768 + (it & 1)*16384;
        #pragma unroll
        for (int kt = 0; kt < 4; kt++) {
            uint32_t afr[2][4];
            #pragma unroll
            for (int mt = 0; mt < 2; mt++) {
                int m = warp_m*32 + mt*16 + (lane & 15);
                int kb = kt*32 + ((lane >> 4) << 4);
                ldmx4(afr[mt], smA + swz(m*128 + kb));
            }
            uint32_t bfr[4][4];
            #pragma unroll
            for (int np = 0; np < 4; np++) {
                int n = warp_n*64 + np*16 + (lane & 7) + ((lane >> 4) << 3);
                int kb = kt*32 + (((lane >> 3) & 1) << 4);
                ldmx4(bfr[np], smB + swz(n*128 + kb));
            }
            #pragma unroll
            for (int mt = 0; mt < 2; mt++)
                #pragma unroll
                for (int nt = 0; nt < 8; nt++)
                    mma16816(acc[mt][nt], afr[mt], &bfr[nt >> 1][(nt & 1)*2]);
        }
        __syncthreads();
    }

    // epilogue: + bias, write fp32, accumulate BN2 per-channel stats
    float sc[8][2], sc2[8][2];
    #pragma unroll
    for (int nt = 0; nt < 8; nt++)
        #pragma unroll
        for (int j = 0; j < 2; j++) { sc[nt][j] = 0.f; sc2[nt][j] = 0.f; }

    #pragma unroll
    for (int mt = 0; mt < 2; mt++) {
        int row = tile_m*128 + warp_m*32 + mt*16 + (lane >> 2);
        #pragma unroll
        for (int nt = 0; nt < 8; nt++) {
            int col = tile_n*128 + warp_n*64 + nt*8 + ((lane & 3) << 1);
            float b0 = g_bias[col], b1 = g_bias[col + 1];
            float2 v0 = make_float2(acc[mt][nt][0] + b0, acc[mt][nt][1] + b1);
            float2 v1 = make_float2(acc[mt][nt][2] + b0, acc[mt][nt][3] + b1);
            *(float2*)&out[(size_t)row*COUT + col]       = v0;
            *(float2*)&out[(size_t)(row + 8)*COUT + col] = v1;
            sc[nt][0]  += v0.x + v1.x;           sc[nt][1]  += v0.y + v1.y;
            sc2[nt][0] += v0.x*v0.x + v1.x*v1.x; sc2[nt][1] += v0.y*v0.y + v1.y*v1.y;
        }
    }
    #pragma unroll
    for (int off = 4; off < 32; off <<= 1) {
        #pragma unroll
        for (int nt = 0; nt < 8; nt++)
            #pragma unroll
            for (int j = 0; j < 2; j++) {
                sc[nt][j]  += __shfl_xor_sync(0xffffffffu, sc[nt][j],  off);
                sc2[nt][j] += __shfl_xor_sync(0xffffffffu, sc2[nt][j], off);
            }
    }
    if (lane < 4) {
        #pragma unroll
        for (int nt = 0; nt < 8; nt++)
            #pragma unroll
            for (int j = 0; j < 2; j++) {
                int col = tile_n*128 + warp_n*64 + nt*8 + lane*2 + j;
                atomicAdd(&g_stats2[col], sc[nt][j]);
                atomicAdd(&g_stats2[COUT + col], sc2[nt][j]);
            }
    }
}

// BN2 fold + apply + relu fused (per-block recompute of scale/shift)
__global__ void __launch_bounds__(256) k_bn2_apply(float* __restrict__ out,
                                                   const float* __restrict__ g2,
                                                   const float* __restrict__ b2) {
    __shared__ float sa[COUT], sd[COUT];
    int t = threadIdx.x;
    const float inv = 1.0f / (float)MROWS;
    #pragma unroll
    for (int i = t; i < COUT; i += 256) {
        float mean = g_stats2[i] * inv;
        float var  = g_stats2[COUT + i] * inv - mean * mean;
        float a = g2[i] * rsqrtf(var + 1e-5f);
        sa[i] = a;
        sd[i] = b2[i] - mean * a;
    }
    __syncthreads();
    #pragma unroll
    for (int it = 0; it < 6; it++) {
        size_t idx4 = (size_t)blockIdx.x * 256 + t + (size_t)it * 524288;
        int o = (int)(idx4 & (COUT/4 - 1)) * 4;
        float4 v = ((float4*)out)[idx4];
        v.x = fmaxf(0.f, v.x * sa[o+0] + sd[o+0]);
        v.y = fmaxf(0.f, v.y * sa[o+1] + sd[o+1]);
        v.z = fmaxf(0.f, v.z * sa[o+2] + sd[o+2]);
        v.w = fmaxf(0.f, v.w * sa[o+3] + sd[o+3]);
        ((float4*)out)[idx4] = v;
    }
}

// ---------------- launch ----------------
extern "C" void kernel_launch(void* const* d_in, const int* in_sizes, int n_in,
                              void* d_out, int out_size) {
    const float* x     = (const float*)d_in[0];   // (B,N,C)
    const float* loc   = (const float*)d_in[1];   // (B,N,2)
    const int*   idxa  = (const int*)  d_in[2];   // (B,N)
    const int*   idxat = (const int*)  d_in[5];   // (B,N)
    const float* wt    = (const float*)d_in[6];   // (B,N,1)
    const float* dwc   = (const float*)d_in[9];   // (C,1,3,3)
    const float* dws   = (const float*)d_in[10];  // (C,1,1,1)
    const float* g1    = (const float*)d_in[11];
    const float* b1    = (const float*)d_in[12];
    const float* cw    = (const float*)d_in[13];  // (CO,C)
    const float* g2    = (const float*)d_in[14];
    const float* b2    = (const float*)d_in[15];
    float* out = (float*)d_out;

    const int GEMM_SMEM = 65536 + 1024;
    cudaFuncSetAttribute(k_gemm_mma, cudaFuncAttributeMaxDynamicSharedMemorySize, GEMM_SMEM);

    k_zero<<<2048, 256>>>();
    k_fill<<<NTOT/256, 256>>>(loc, idxa, idxat, wt);
    k_mapgather<<<BB*HWC/4, 256>>>(x);
    k_dwconv<<<BB*H2*6, 256>>>(dwc);
    k_scatter2<<<NTOT/16, 256>>>(x, loc, idxa, idxat, wt, dws);
    k_bn1pack<<<MROWS/64, 256>>>();
    k_foldpack<<<COUT, CC>>>(cw, g1, b1);
    k_gemm_mma<<<(MROWS/128)*(COUT/128), 256, GEMM_SMEM>>>(out);
    k_bn2_apply<<<2048, 256>>>(out, g2, b2);
}